// round 5
// baseline (speedup 1.0000x reference)
#include <cuda_runtime.h>

#define D 256
#define MAXN 100000
#define BM 64
#define KT 16
#define PA 20      // As row stride (floats): banks (20g+t)%32 all distinct
#define PBN 264    // Bs row stride (floats): banks (8*tig+grp)%32 distinct
#define PH 260     // hid row stride (floats): banks (4g+t)%32 distinct

#define ASZ (BM * PA)        // 1280 floats per A buffer
#define BSZ (KT * PBN)       // 4224 floats per B buffer
#define SM_BS (2 * ASZ)                // Bs offset (floats)
#define SM_HID (2 * ASZ + 2 * BSZ)     // hid offset (floats)
#define SMEM_BYTES ((2 * ASZ + 2 * BSZ + BM * PH) * 4)  // 110592 B

// Scratch (allocation-free rule: __device__ globals)
__device__ float g_msg[(size_t)MAXN * D];
__device__ float g_deg[MAXN];
__device__ float g_tmp[(size_t)MAXN * D];

// ---------------------------------------------------------------------------
__global__ void zero_kernel(float* __restrict__ msg, float* __restrict__ deg, int n) {
    int total4 = n * (D / 4);
    float4 z = make_float4(0.f, 0.f, 0.f, 0.f);
    float4* m4 = (float4*)msg;
    for (int i = blockIdx.x * blockDim.x + threadIdx.x; i < total4;
         i += gridDim.x * blockDim.x)
        m4[i] = z;
    for (int i = blockIdx.x * blockDim.x + threadIdx.x; i < n;
         i += gridDim.x * blockDim.x)
        deg[i] = 0.f;
}

// ---------------------------------------------------------------------------
__device__ __forceinline__ void red_add_v4(float* p, float4 v) {
    asm volatile("red.global.add.v4.f32 [%0], {%1,%2,%3,%4};"
                 :: "l"(p), "f"(v.x), "f"(v.y), "f"(v.z), "f"(v.w) : "memory");
}

// warp-per-edge scatter: each lane gathers 2 float4, 2 vector red ops.
__global__ __launch_bounds__(256) void scatter_kernel(
        const float* __restrict__ feat,
        const int* __restrict__ src,
        const int* __restrict__ dst,
        float* __restrict__ msg,
        float* __restrict__ deg,
        int nE) {
    int warp = (blockIdx.x * blockDim.x + threadIdx.x) >> 5;
    int lane = threadIdx.x & 31;
    if (warp >= nE) return;
    int s = __ldg(src + warp), d = __ldg(dst + warp);
    const float4* f4 = (const float4*)(feat + (size_t)s * D);
    float* mrow = msg + (size_t)d * D;
    float4 v0 = __ldg(f4 + lane);
    float4 v1 = __ldg(f4 + lane + 32);
    red_add_v4(mrow + 4 * lane, v0);
    red_add_v4(mrow + 4 * (lane + 32), v1);
    if (lane == 0) atomicAdd(&deg[d], 1.0f);
}

// ---------------------------------------------------------------------------
__device__ __forceinline__ void mma_tf32(float* c, const unsigned* a,
                                         unsigned b0, unsigned b1) {
    asm volatile(
        "mma.sync.aligned.m16n8k8.row.col.f32.tf32.tf32.f32 "
        "{%0,%1,%2,%3}, {%4,%5,%6,%7}, {%8,%9}, {%0,%1,%2,%3};"
        : "+f"(c[0]), "+f"(c[1]), "+f"(c[2]), "+f"(c[3])
        : "r"(a[0]), "r"(a[1]), "r"(a[2]), "r"(a[3]), "r"(b0), "r"(b1));
}

__device__ __forceinline__ void cp16(unsigned dst, const void* src, int nbytes) {
    asm volatile("cp.async.cg.shared.global [%0], [%1], 16, %2;"
                 :: "r"(dst), "l"(src), "r"(nbytes));
}
__device__ __forceinline__ void cp_commit() {
    asm volatile("cp.async.commit_group;");
}
template <int N>
__device__ __forceinline__ void cp_wait() {
    asm volatile("cp.async.wait_group %0;" :: "n"(N));
}

// ---------------------------------------------------------------------------
// Fused MLP: out = [h, msg*rdeg] @ W1 + b1 -> relu -> @ W2 + b2 -> +h -> (LN)
// 64 rows x 256 cols per block. 8 warps as 2 wm x 4 wn: each warp m=32, n=64,
// so B fragments load once per kb and serve two m16 tiles (48 LDS / 32 MMA
// per KT=16 step). tf32 mma, cp.async double-buffered, 2 CTAs/SM.
__global__ __launch_bounds__(256, 2) void mlp_mma_kernel(
    const float* __restrict__ h,
    const float* __restrict__ msg,
    const float* __restrict__ deg,
    const float* __restrict__ w1, const float* __restrict__ b1,
    const float* __restrict__ w2, const float* __restrict__ b2,
    const float* __restrict__ lng, const float* __restrict__ lnb,
    float* __restrict__ out, int M, int use_ln)
{
    extern __shared__ float smf[];
    float* As  = smf;             // [2][64][PA]
    float* Bs  = smf + SM_BS;     // [2][KT][PBN]
    float* hid = smf + SM_HID;    // [64][PH]
    unsigned sbase = (unsigned)__cvta_generic_to_shared(smf);
    unsigned As_s = sbase;
    unsigned Bs_s = sbase + SM_BS * 4;

    int tid = threadIdx.x;
    int lane = tid & 31, w = tid >> 5;
    int grp = lane >> 2, tig = lane & 3;
    int wm = w & 1, wn = w >> 1;
    int m0 = wm * 32;
    int nbase = wn * 64;
    int row0 = blockIdx.x * BM;

    // degree reciprocals for this thread's four A rows (m0+grp+8i)
    float rd[4];
#pragma unroll
    for (int i = 0; i < 4; i++) {
        int rA = row0 + m0 + 8 * i + grp;
        rd[i] = (rA < M) ? (1.f / fmaxf(__ldg(deg + rA), 1.f)) : 1.f;
    }

    float acc[2][8][4];
#pragma unroll
    for (int mt = 0; mt < 2; mt++)
#pragma unroll
        for (int i = 0; i < 8; i++)
#pragma unroll
            for (int j = 0; j < 4; j++) acc[mt][i][j] = 0.f;

    // --- cp.async producer indices ---
    int arow = tid >> 2, achunk = tid & 3;            // A: 64 rows x 16 floats
    int aval = (row0 + arow < M) ? 16 : 0;
    int arowc = (row0 + arow < M) ? (row0 + arow) : (M - 1);
    unsigned a_dst0 = As_s + (unsigned)(arow * PA + achunk * 4) * 4;
    int bk = tid >> 4, bseg = tid & 15;               // B: 16 rows x 256 floats
    unsigned b_dst0 = Bs_s + (unsigned)(bk * PBN + bseg * 16) * 4;

    auto issueA = [&](int s, int buf) {
        int k0 = s * KT;
        const float* srcp = (k0 < D)
            ? (h   + (size_t)arowc * D + k0 + achunk * 4)
            : (msg + (size_t)arowc * D + (k0 - D) + achunk * 4);
        cp16(a_dst0 + buf * (ASZ * 4), srcp, aval);
    };
    auto issueB = [&](const float* __restrict__ W, int s, int buf) {
        const float* srcp = W + (size_t)(s * KT + bk) * D + bseg * 16;
        unsigned dst = b_dst0 + buf * (BSZ * 4);
#pragma unroll
        for (int i = 0; i < 4; i++)
            cp16(dst + 16 * i, srcp + 4 * i, 16);
    };

    auto computeStep = [&](const float* __restrict__ Ab, int astride, int kbase,
                           const float* __restrict__ Bb, bool scaleA) {
#pragma unroll
        for (int kb = 0; kb < 2; kb++) {
            int lk = kb * 8 + tig;
            int kc = kbase + lk;
            // B fragments once per kb, reused across both m16 tiles
            float br0[8], br1[8];
            const float* B0 = Bb + lk * PBN;
            const float* B1 = Bb + (lk + 4) * PBN;
#pragma unroll
            for (int t2 = 0; t2 < 8; t2++) {
                int n = nbase + 8 * t2 + grp;
                br0[t2] = B0[n];
                br1[t2] = B1[n];
            }
#pragma unroll
            for (int mt = 0; mt < 2; mt++) {
                int mr = m0 + 16 * mt + grp;
                float a0 = Ab[mr * astride + kc];
                float a1 = Ab[(mr + 8) * astride + kc];
                float a2 = Ab[mr * astride + kc + 4];
                float a3 = Ab[(mr + 8) * astride + kc + 4];
                if (scaleA) {
                    a0 *= rd[2 * mt]; a2 *= rd[2 * mt];
                    a1 *= rd[2 * mt + 1]; a3 *= rd[2 * mt + 1];
                }
                unsigned au[4] = {__float_as_uint(a0), __float_as_uint(a1),
                                  __float_as_uint(a2), __float_as_uint(a3)};
#pragma unroll
                for (int t2 = 0; t2 < 8; t2++)
                    mma_tf32(acc[mt][t2], au,
                             __float_as_uint(br0[t2]), __float_as_uint(br1[t2]));
            }
        }
    };

    // ---- phase 1: hidden = relu(x @ W1 + b1), K = 512, 32 steps ----
    issueA(0, 0); issueB(w1, 0, 0); cp_commit();
#pragma unroll 1
    for (int s = 0; s < 32; s++) {
        if (s < 31) {
            issueA(s + 1, (s + 1) & 1); issueB(w1, s + 1, (s + 1) & 1);
            cp_commit();
            cp_wait<1>();
        } else {
            cp_wait<0>();
        }
        __syncthreads();
        computeStep(As + (s & 1) * ASZ, PA, 0, Bs + (s & 1) * BSZ, s >= 16);
        __syncthreads();
    }

    // prefetch first W2 tile while doing epilogue 1
    issueB(w2, 0, 0); cp_commit();

    // epilogue 1: bias + relu -> hid; reset acc
#pragma unroll
    for (int mt = 0; mt < 2; mt++)
#pragma unroll
    for (int t2 = 0; t2 < 8; t2++) {
        int c = nbase + 8 * t2 + 2 * tig;
        int mr = m0 + 16 * mt + grp;
        float bb0 = __ldg(b1 + c), bb1 = __ldg(b1 + c + 1);
        hid[mr * PH + c]           = fmaxf(acc[mt][t2][0] + bb0, 0.f);
        hid[mr * PH + c + 1]       = fmaxf(acc[mt][t2][1] + bb1, 0.f);
        hid[(mr + 8) * PH + c]     = fmaxf(acc[mt][t2][2] + bb0, 0.f);
        hid[(mr + 8) * PH + c + 1] = fmaxf(acc[mt][t2][3] + bb1, 0.f);
#pragma unroll
        for (int j = 0; j < 4; j++) acc[mt][t2][j] = 0.f;
    }

    // ---- phase 2: acc = hid @ W2, K = 256, 16 steps ----
#pragma unroll 1
    for (int s = 0; s < 16; s++) {
        if (s < 15) {
            issueB(w2, s + 1, (s + 1) & 1);
            cp_commit();
            cp_wait<1>();
        } else {
            cp_wait<0>();
        }
        __syncthreads();   // s==0: also publishes epilogue-1 hid writes
        computeStep(hid, PH, s * KT, Bs + (s & 1) * BSZ, false);
        __syncthreads();
    }

    // epilogue 2: raw acc -> hid (all phase-2 reads finished at loop's last sync)
#pragma unroll
    for (int mt = 0; mt < 2; mt++)
#pragma unroll
    for (int t2 = 0; t2 < 8; t2++) {
        int c = nbase + 8 * t2 + 2 * tig;
        int mr = m0 + 16 * mt + grp;
        hid[mr * PH + c]           = acc[mt][t2][0];
        hid[mr * PH + c + 1]       = acc[mt][t2][1];
        hid[(mr + 8) * PH + c]     = acc[mt][t2][2];
        hid[(mr + 8) * PH + c + 1] = acc[mt][t2][3];
    }
    __syncthreads();

    // output pass: + b2 + residual (+ LN), coalesced; warp w owns rows 8w..8w+7
    for (int q = 0; q < 8; q++) {
        int r = w * 8 + q;
        int row = row0 + r;
        if (row >= M) continue;
        float v[8];
        float sum = 0.f, sq = 0.f;
#pragma unroll
        for (int j = 0; j < 8; j++) {
            int c = lane + 32 * j;
            float x = hid[r * PH + c] + __ldg(b2 + c) + h[(size_t)row * D + c];
            v[j] = x; sum += x; sq += x * x;
        }
        if (use_ln) {
#pragma unroll
            for (int o = 16; o > 0; o >>= 1) {
                sum += __shfl_xor_sync(0xffffffffu, sum, o);
                sq  += __shfl_xor_sync(0xffffffffu, sq, o);
            }
            float mean = sum * (1.f / D);
            float var  = sq * (1.f / D) - mean * mean;
            float rstd = rsqrtf(var + 1e-5f);
#pragma unroll
            for (int j = 0; j < 8; j++) {
                int c = lane + 32 * j;
                v[j] = (v[j] - mean) * rstd * __ldg(lng + c) + __ldg(lnb + c);
            }
        }
#pragma unroll
        for (int j = 0; j < 8; j++)
            out[(size_t)row * D + lane + 32 * j] = v[j];
    }
}

// ---------------------------------------------------------------------------
static inline int cdiv(int a, int b) { return (a + b - 1) / b; }

extern "C" void kernel_launch(void* const* d_in, const int* in_sizes, int n_in,
                              void* d_out, int out_size) {
    const float* cell_h = (const float*)d_in[0];
    const float* net_h  = (const float*)d_in[1];
    const int* e_c2n = (const int*)d_in[2];
    const int* e_n2c = (const int*)d_in[3];
    const int* e_c2c = (const int*)d_in[4];
    const float* c2n_w1 = (const float*)d_in[5];
    const float* c2n_b1 = (const float*)d_in[6];
    const float* c2n_w2 = (const float*)d_in[7];
    const float* c2n_b2 = (const float*)d_in[8];
    const float* n2c_w1 = (const float*)d_in[9];
    const float* n2c_b1 = (const float*)d_in[10];
    const float* n2c_w2 = (const float*)d_in[11];
    const float* n2c_b2 = (const float*)d_in[12];
    const float* c2c_w1 = (const float*)d_in[13];
    const float* c2c_b1 = (const float*)d_in[14];
    const float* c2c_w2 = (const float*)d_in[15];
    const float* c2c_b2 = (const float*)d_in[16];
    const float* net_ln_g  = (const float*)d_in[17];
    const float* net_ln_b  = (const float*)d_in[18];
    const float* cell_ln_g = (const float*)d_in[19];
    const float* cell_ln_b = (const float*)d_in[20];

    int n_cell = in_sizes[0] / D;
    int n_net  = in_sizes[1] / D;
    int E1 = in_sizes[2] / 2;
    int E2 = in_sizes[3] / 2;
    int E3 = in_sizes[4] / 2;

    float* out = (float*)d_out;
    float* out_cell = out;
    float* out_net  = out + (size_t)n_cell * D;

    static float* p_msg = nullptr;
    static float* p_deg = nullptr;
    static float* p_tmp = nullptr;
    if (!p_msg) {
        cudaGetSymbolAddress((void**)&p_msg, g_msg);
        cudaGetSymbolAddress((void**)&p_deg, g_deg);
        cudaGetSymbolAddress((void**)&p_tmp, g_tmp);
        cudaFuncSetAttribute(mlp_mma_kernel,
                             cudaFuncAttributeMaxDynamicSharedMemorySize,
                             SMEM_BYTES);
    }

    // Stage 1: cells -> nets, net_h' = LN(net_h + MLP([net_h, mean_msg]))
    zero_kernel<<<1024, 256>>>(p_msg, p_deg, n_net);
    scatter_kernel<<<cdiv(E1 * 32, 256), 256>>>(cell_h, e_c2n, e_c2n + E1,
                                                p_msg, p_deg, E1);
    mlp_mma_kernel<<<cdiv(n_net, BM), 256, SMEM_BYTES>>>(
        net_h, p_msg, p_deg, c2n_w1, c2n_b1, c2n_w2, c2n_b2,
        net_ln_g, net_ln_b, out_net, n_net, 1);

    // Stage 2: nets -> cells, cell_tmp = cell_h + MLP([cell_h, mean_msg])
    zero_kernel<<<1024, 256>>>(p_msg, p_deg, n_cell);
    scatter_kernel<<<cdiv(E2 * 32, 256), 256>>>(out_net, e_n2c, e_n2c + E2,
                                                p_msg, p_deg, E2);
    mlp_mma_kernel<<<cdiv(n_cell, BM), 256, SMEM_BYTES>>>(
        cell_h, p_msg, p_deg, n2c_w1, n2c_b1, n2c_w2, n2c_b2,
        (const float*)0, (const float*)0, p_tmp, n_cell, 0);

    // Stage 3: cells -> cells, cell_h' = LN(cell_tmp + MLP([cell_tmp, mean_msg]))
    zero_kernel<<<1024, 256>>>(p_msg, p_deg, n_cell);
    scatter_kernel<<<cdiv(E3 * 32, 256), 256>>>(p_tmp, e_c2c, e_c2c + E3,
                                                p_msg, p_deg, E3);
    mlp_mma_kernel<<<cdiv(n_cell, BM), 256, SMEM_BYTES>>>(
        p_tmp, p_msg, p_deg, c2c_w1, c2c_b1, c2c_w2, c2c_b2,
        cell_ln_g, cell_ln_b, out_cell, n_cell, 1);
}

// round 6
// speedup vs baseline: 1.5557x; 1.5557x over previous
#include <cuda_runtime.h>

#define D 256
#define MAXN 100000
#define MAXE 301056
#define BM 64
#define KT 16
#define PA 20      // As row stride (floats): banks (20g+t)%32 all distinct
#define PBN 264    // Bs row stride (floats): banks (8*tig+grp)%32 distinct
#define PH 260     // hid row stride (floats): banks (4g+t)%32 distinct

#define ASZ (BM * PA)        // 1280 floats per A buffer
#define BSZ (KT * PBN)       // 4224 floats per B buffer
#define SM_BS (2 * ASZ)                // Bs offset (floats)
#define SM_HID (2 * ASZ + 2 * BSZ)     // hid offset (floats)
#define SMEM_BYTES ((2 * ASZ + 2 * BSZ + BM * PH) * 4)  // 110592 B

// Scratch (allocation-free rule: __device__ globals)
__device__ float g_msg[(size_t)MAXN * D];
__device__ float g_tmp[(size_t)MAXN * D];
__device__ int   g_offs[MAXN + 1];
__device__ int   g_cur[MAXN];
__device__ int   g_eid[MAXE];
__device__ int   g_aux[128];
__device__ int   g_total;

// ---------------------------------------------------------------------------
__global__ void zero_int_kernel(int* __restrict__ p, int n) {
    for (int i = blockIdx.x * blockDim.x + threadIdx.x; i < n;
         i += gridDim.x * blockDim.x)
        p[i] = 0;
}

// count edges per dst
__global__ void count_kernel(const int* __restrict__ dst, int* __restrict__ cnt,
                             int nE) {
    for (int e = blockIdx.x * blockDim.x + threadIdx.x; e < nE;
         e += gridDim.x * blockDim.x)
        atomicAdd(&cnt[dst[e]], 1);
}

// in-place exclusive scan of 1024-elem blocks; aux[b] = block total
__global__ __launch_bounds__(256) void scan_block_kernel(
        int* __restrict__ data, int* __restrict__ aux, int n) {
    __shared__ int wsum[8];
    int t = threadIdx.x;
    int base = blockIdx.x * 1024 + t * 4;
    int v[4];
#pragma unroll
    for (int k = 0; k < 4; k++) v[k] = (base + k < n) ? data[base + k] : 0;
    int tsum = v[0] + v[1] + v[2] + v[3];
    int lane = t & 31, wid = t >> 5;
    int x = tsum;
#pragma unroll
    for (int o = 1; o < 32; o <<= 1) {
        int y = __shfl_up_sync(0xffffffffu, x, o);
        if (lane >= o) x += y;
    }
    int wexc = x - tsum;
    if (lane == 31) wsum[wid] = x;
    __syncthreads();
    if (t == 0) {
        int run = 0;
#pragma unroll
        for (int i = 0; i < 8; i++) { int s = wsum[i]; wsum[i] = run; run += s; }
        aux[blockIdx.x] = run;
    }
    __syncthreads();
    int run = wsum[wid] + wexc;
#pragma unroll
    for (int k = 0; k < 4; k++) {
        if (base + k < n) data[base + k] = run;
        run += v[k];
    }
}

// exclusive scan of aux (nb <= 128), one block of 128 threads
__global__ void scan_aux_kernel(int* __restrict__ aux, int nb,
                                int* __restrict__ total) {
    __shared__ int s[128];
    int t = threadIdx.x;
    int v = (t < nb) ? aux[t] : 0;
    s[t] = v;
    __syncthreads();
    for (int o = 1; o < 128; o <<= 1) {
        int y = (t >= o) ? s[t - o] : 0;
        __syncthreads();
        s[t] += y;
        __syncthreads();
    }
    if (t < nb) aux[t] = s[t] - v;
    if (t == 127) *total = s[127];
}

// offs[i] += aux[i/1024]; cur = offs; offs[n] = total
__global__ void finalize_kernel(int* __restrict__ offs, const int* __restrict__ aux,
                                int* __restrict__ cur, int n,
                                const int* __restrict__ total) {
    int i = blockIdx.x * blockDim.x + threadIdx.x;
    if (i < n) {
        int v = offs[i] + aux[i >> 10];
        offs[i] = v;
        cur[i] = v;
    }
    if (i == 0) offs[n] = *total;
}

// bucket fill: eid[pos within dst bucket] = src
__global__ void fill_kernel(const int* __restrict__ src, const int* __restrict__ dst,
                            int* __restrict__ cur, int* __restrict__ eid, int nE) {
    for (int e = blockIdx.x * blockDim.x + threadIdx.x; e < nE;
         e += gridDim.x * blockDim.x) {
        int p = atomicAdd(&cur[dst[e]], 1);
        eid[p] = src[e];
    }
}

// warp per dst: msg[d] = mean of feat[src] over bucket (0 if empty)
__global__ __launch_bounds__(256) void gather_kernel(
        const float* __restrict__ feat, const int* __restrict__ offs,
        const int* __restrict__ eid, float* __restrict__ msg, int n) {
    int w = (blockIdx.x * blockDim.x + threadIdx.x) >> 5;
    int lane = threadIdx.x & 31;
    if (w >= n) return;
    int s0 = __ldg(offs + w), s1 = __ldg(offs + w + 1);
    float4 a0 = make_float4(0.f, 0.f, 0.f, 0.f);
    float4 a1 = make_float4(0.f, 0.f, 0.f, 0.f);
    int j = s0;
    for (; j + 1 < s1; j += 2) {
        int e0 = __ldg(eid + j), e1 = __ldg(eid + j + 1);
        const float4* r0 = (const float4*)(feat + (size_t)e0 * D);
        const float4* r1 = (const float4*)(feat + (size_t)e1 * D);
        float4 x0 = __ldg(r0 + lane), x1 = __ldg(r0 + lane + 32);
        float4 y0 = __ldg(r1 + lane), y1 = __ldg(r1 + lane + 32);
        a0.x += x0.x + y0.x; a0.y += x0.y + y0.y;
        a0.z += x0.z + y0.z; a0.w += x0.w + y0.w;
        a1.x += x1.x + y1.x; a1.y += x1.y + y1.y;
        a1.z += x1.z + y1.z; a1.w += x1.w + y1.w;
    }
    if (j < s1) {
        int e0 = __ldg(eid + j);
        const float4* r0 = (const float4*)(feat + (size_t)e0 * D);
        float4 x0 = __ldg(r0 + lane), x1 = __ldg(r0 + lane + 32);
        a0.x += x0.x; a0.y += x0.y; a0.z += x0.z; a0.w += x0.w;
        a1.x += x1.x; a1.y += x1.y; a1.z += x1.z; a1.w += x1.w;
    }
    float r = 1.f / (float)max(s1 - s0, 1);
    a0.x *= r; a0.y *= r; a0.z *= r; a0.w *= r;
    a1.x *= r; a1.y *= r; a1.z *= r; a1.w *= r;
    float4* mrow = (float4*)(msg + (size_t)w * D);
    mrow[lane] = a0;
    mrow[lane + 32] = a1;
}

// ---------------------------------------------------------------------------
__device__ __forceinline__ void mma_tf32(float* c, const unsigned* a,
                                         unsigned b0, unsigned b1) {
    asm volatile(
        "mma.sync.aligned.m16n8k8.row.col.f32.tf32.tf32.f32 "
        "{%0,%1,%2,%3}, {%4,%5,%6,%7}, {%8,%9}, {%0,%1,%2,%3};"
        : "+f"(c[0]), "+f"(c[1]), "+f"(c[2]), "+f"(c[3])
        : "r"(a[0]), "r"(a[1]), "r"(a[2]), "r"(a[3]), "r"(b0), "r"(b1));
}

__device__ __forceinline__ void cp16(unsigned dst, const void* src, int nbytes) {
    asm volatile("cp.async.cg.shared.global [%0], [%1], 16, %2;"
                 :: "r"(dst), "l"(src), "r"(nbytes));
}
__device__ __forceinline__ void cp_commit() {
    asm volatile("cp.async.commit_group;");
}
template <int N>
__device__ __forceinline__ void cp_wait() {
    asm volatile("cp.async.wait_group %0;" :: "n"(N));
}

// ---------------------------------------------------------------------------
// Fused MLP (R4-proven config): out = [h, msg] @ W1 + b1 -> relu -> @ W2 + b2
// -> +h -> (LN). 64x256 per block, 8 warps as 4 wm x 2 wn (m=16,n=128 each),
// tf32 mma, cp.async double-buffered, 2 CTAs/SM. msg is pre-normalized.
__global__ __launch_bounds__(256, 2) void mlp_mma_kernel(
    const float* __restrict__ h,
    const float* __restrict__ msg,
    const float* __restrict__ w1, const float* __restrict__ b1,
    const float* __restrict__ w2, const float* __restrict__ b2,
    const float* __restrict__ lng, const float* __restrict__ lnb,
    float* __restrict__ out, int M, int use_ln)
{
    extern __shared__ float smf[];
    float* As  = smf;             // [2][64][PA]
    float* Bs  = smf + SM_BS;     // [2][KT][PBN]
    float* hid = smf + SM_HID;    // [64][PH]
    unsigned sbase = (unsigned)__cvta_generic_to_shared(smf);
    unsigned As_s = sbase;
    unsigned Bs_s = sbase + SM_BS * 4;

    int tid = threadIdx.x;
    int lane = tid & 31, w = tid >> 5;
    int grp = lane >> 2, tig = lane & 3;
    int wm = w & 3, wn = w >> 2;
    int m0 = wm * 16;
    int nbase = wn * 128;
    int row0 = blockIdx.x * BM;

    float acc[16][4];
#pragma unroll
    for (int i = 0; i < 16; i++)
#pragma unroll
        for (int j = 0; j < 4; j++) acc[i][j] = 0.f;

    // --- cp.async producer indices ---
    int arow = tid >> 2, achunk = tid & 3;            // A: 64 rows x 16 floats
    int aval = (row0 + arow < M) ? 16 : 0;
    int arowc = (row0 + arow < M) ? (row0 + arow) : (M - 1);
    unsigned a_dst0 = As_s + (unsigned)(arow * PA + achunk * 4) * 4;
    int bk = tid >> 4, bseg = tid & 15;               // B: 16 rows x 256 floats
    unsigned b_dst0 = Bs_s + (unsigned)(bk * PBN + bseg * 16) * 4;

    auto issueA = [&](int s, int buf) {
        int k0 = s * KT;
        const float* srcp = (k0 < D)
            ? (h   + (size_t)arowc * D + k0 + achunk * 4)
            : (msg + (size_t)arowc * D + (k0 - D) + achunk * 4);
        cp16(a_dst0 + buf * (ASZ * 4), srcp, aval);
    };
    auto issueB = [&](const float* __restrict__ W, int s, int buf) {
        const float* srcp = W + (size_t)(s * KT + bk) * D + bseg * 16;
        unsigned dst = b_dst0 + buf * (BSZ * 4);
#pragma unroll
        for (int i = 0; i < 4; i++)
            cp16(dst + 16 * i, srcp + 4 * i, 16);
    };

    auto computeStep = [&](const float* __restrict__ Ab, int astride, int kbase,
                           const float* __restrict__ Bb) {
#pragma unroll
        for (int kb = 0; kb < 2; kb++) {
            int kc = kbase + kb * 8 + tig;
            unsigned au[4];
            au[0] = __float_as_uint(Ab[(m0 + grp) * astride + kc]);
            au[1] = __float_as_uint(Ab[(m0 + grp + 8) * astride + kc]);
            au[2] = __float_as_uint(Ab[(m0 + grp) * astride + kc + 4]);
            au[3] = __float_as_uint(Ab[(m0 + grp + 8) * astride + kc + 4]);
            const float* Br0 = Bb + (kb * 8 + tig) * PBN;
            const float* Br1 = Bb + (kb * 8 + tig + 4) * PBN;
#pragma unroll
            for (int t2 = 0; t2 < 16; t2++) {
                int n = nbase + 8 * t2 + grp;
                mma_tf32(acc[t2], au,
                         __float_as_uint(Br0[n]), __float_as_uint(Br1[n]));
            }
        }
    };

    // ---- phase 1: hidden = relu(x @ W1 + b1), K = 512, 32 steps ----
    issueA(0, 0); issueB(w1, 0, 0); cp_commit();
#pragma unroll 1
    for (int s = 0; s < 32; s++) {
        if (s < 31) {
            issueA(s + 1, (s + 1) & 1); issueB(w1, s + 1, (s + 1) & 1);
            cp_commit();
            cp_wait<1>();
        } else {
            cp_wait<0>();
        }
        __syncthreads();
        computeStep(As + (s & 1) * ASZ, PA, 0, Bs + (s & 1) * BSZ);
        __syncthreads();
    }

    // prefetch first W2 tile while doing epilogue 1
    issueB(w2, 0, 0); cp_commit();

    // epilogue 1: bias + relu -> hid; reset acc
#pragma unroll
    for (int t2 = 0; t2 < 16; t2++) {
        int c = nbase + 8 * t2 + 2 * tig;
        float bb0 = __ldg(b1 + c), bb1 = __ldg(b1 + c + 1);
        hid[(m0 + grp) * PH + c]         = fmaxf(acc[t2][0] + bb0, 0.f);
        hid[(m0 + grp) * PH + c + 1]     = fmaxf(acc[t2][1] + bb1, 0.f);
        hid[(m0 + grp + 8) * PH + c]     = fmaxf(acc[t2][2] + bb0, 0.f);
        hid[(m0 + grp + 8) * PH + c + 1] = fmaxf(acc[t2][3] + bb1, 0.f);
#pragma unroll
        for (int j = 0; j < 4; j++) acc[t2][j] = 0.f;
    }

    // ---- phase 2: acc = hid @ W2, K = 256, 16 steps ----
#pragma unroll 1
    for (int s = 0; s < 16; s++) {
        if (s < 15) {
            issueB(w2, s + 1, (s + 1) & 1);
            cp_commit();
            cp_wait<1>();
        } else {
            cp_wait<0>();
        }
        __syncthreads();   // s==0: also publishes epilogue-1 hid writes
        computeStep(hid, PH, s * KT, Bs + (s & 1) * BSZ);
        __syncthreads();
    }

    // epilogue 2: raw acc -> hid
#pragma unroll
    for (int t2 = 0; t2 < 16; t2++) {
        int c = nbase + 8 * t2 + 2 * tig;
        hid[(m0 + grp) * PH + c]         = acc[t2][0];
        hid[(m0 + grp) * PH + c + 1]     = acc[t2][1];
        hid[(m0 + grp + 8) * PH + c]     = acc[t2][2];
        hid[(m0 + grp + 8) * PH + c + 1] = acc[t2][3];
    }
    __syncthreads();

    // output pass: + b2 + residual (+ LN), coalesced; warp w owns rows 8w..8w+7
    for (int q = 0; q < 8; q++) {
        int r = w * 8 + q;
        int row = row0 + r;
        if (row >= M) continue;
        float v[8];
        float sum = 0.f, sq = 0.f;
#pragma unroll
        for (int j = 0; j < 8; j++) {
            int c = lane + 32 * j;
            float x = hid[r * PH + c] + __ldg(b2 + c) + h[(size_t)row * D + c];
            v[j] = x; sum += x; sq += x * x;
        }
        if (use_ln) {
#pragma unroll
            for (int o = 16; o > 0; o >>= 1) {
                sum += __shfl_xor_sync(0xffffffffu, sum, o);
                sq  += __shfl_xor_sync(0xffffffffu, sq, o);
            }
            float mean = sum * (1.f / D);
            float var  = sq * (1.f / D) - mean * mean;
            float rstd = rsqrtf(var + 1e-5f);
#pragma unroll
            for (int j = 0; j < 8; j++) {
                int c = lane + 32 * j;
                v[j] = (v[j] - mean) * rstd * __ldg(lng + c) + __ldg(lnb + c);
            }
        }
#pragma unroll
        for (int j = 0; j < 8; j++)
            out[(size_t)row * D + lane + 32 * j] = v[j];
    }
}

// ---------------------------------------------------------------------------
static inline int cdiv(int a, int b) { return (a + b - 1) / b; }

struct Scratch {
    float *msg, *tmp;
    int *offs, *cur, *eid, *aux, *total;
};

static void aggregate(const float* feat, const int* src, const int* dst,
                      int nE, int n, const Scratch& S) {
    int nb = cdiv(n, 1024);
    zero_int_kernel<<<cdiv(n + 1, 256), 256>>>(S.offs, n + 1);
    count_kernel<<<cdiv(nE, 256), 256>>>(dst, S.offs, nE);
    scan_block_kernel<<<nb, 256>>>(S.offs, S.aux, n);
    scan_aux_kernel<<<1, 128>>>(S.aux, nb, S.total);
    finalize_kernel<<<cdiv(n, 256), 256>>>(S.offs, S.aux, S.cur, n, S.total);
    fill_kernel<<<cdiv(nE, 256), 256>>>(src, dst, S.cur, S.eid, nE);
    gather_kernel<<<cdiv(n * 32, 256), 256>>>(feat, S.offs, S.eid, S.msg, n);
}

extern "C" void kernel_launch(void* const* d_in, const int* in_sizes, int n_in,
                              void* d_out, int out_size) {
    const float* cell_h = (const float*)d_in[0];
    const float* net_h  = (const float*)d_in[1];
    const int* e_c2n = (const int*)d_in[2];
    const int* e_n2c = (const int*)d_in[3];
    const int* e_c2c = (const int*)d_in[4];
    const float* c2n_w1 = (const float*)d_in[5];
    const float* c2n_b1 = (const float*)d_in[6];
    const float* c2n_w2 = (const float*)d_in[7];
    const float* c2n_b2 = (const float*)d_in[8];
    const float* n2c_w1 = (const float*)d_in[9];
    const float* n2c_b1 = (const float*)d_in[10];
    const float* n2c_w2 = (const float*)d_in[11];
    const float* n2c_b2 = (const float*)d_in[12];
    const float* c2c_w1 = (const float*)d_in[13];
    const float* c2c_b1 = (const float*)d_in[14];
    const float* c2c_w2 = (const float*)d_in[15];
    const float* c2c_b2 = (const float*)d_in[16];
    const float* net_ln_g  = (const float*)d_in[17];
    const float* net_ln_b  = (const float*)d_in[18];
    const float* cell_ln_g = (const float*)d_in[19];
    const float* cell_ln_b = (const float*)d_in[20];

    int n_cell = in_sizes[0] / D;
    int n_net  = in_sizes[1] / D;
    int E1 = in_sizes[2] / 2;
    int E2 = in_sizes[3] / 2;
    int E3 = in_sizes[4] / 2;

    float* out = (float*)d_out;
    float* out_cell = out;
    float* out_net  = out + (size_t)n_cell * D;

    static Scratch S = {};
    if (!S.msg) {
        cudaGetSymbolAddress((void**)&S.msg, g_msg);
        cudaGetSymbolAddress((void**)&S.tmp, g_tmp);
        cudaGetSymbolAddress((void**)&S.offs, g_offs);
        cudaGetSymbolAddress((void**)&S.cur, g_cur);
        cudaGetSymbolAddress((void**)&S.eid, g_eid);
        cudaGetSymbolAddress((void**)&S.aux, g_aux);
        cudaGetSymbolAddress((void**)&S.total, g_total);
        cudaFuncSetAttribute(mlp_mma_kernel,
                             cudaFuncAttributeMaxDynamicSharedMemorySize,
                             SMEM_BYTES);
    }

    // Stage 1: cells -> nets, net_h' = LN(net_h + MLP([net_h, mean_msg]))
    aggregate(cell_h, e_c2n, e_c2n + E1, E1, n_net, S);
    mlp_mma_kernel<<<cdiv(n_net, BM), 256, SMEM_BYTES>>>(
        net_h, S.msg, c2n_w1, c2n_b1, c2n_w2, c2n_b2,
        net_ln_g, net_ln_b, out_net, n_net, 1);

    // Stage 2: nets -> cells, cell_tmp = cell_h + MLP([cell_h, mean_msg])
    aggregate(out_net, e_n2c, e_n2c + E2, E2, n_cell, S);
    mlp_mma_kernel<<<cdiv(n_cell, BM), 256, SMEM_BYTES>>>(
        cell_h, S.msg, n2c_w1, n2c_b1, n2c_w2, n2c_b2,
        (const float*)0, (const float*)0, S.tmp, n_cell, 0);

    // Stage 3: cells -> cells, cell_h' = LN(cell_tmp + MLP([cell_tmp, mean_msg]))
    aggregate(S.tmp, e_c2c, e_c2c + E3, E3, n_cell, S);
    mlp_mma_kernel<<<cdiv(n_cell, BM), 256, SMEM_BYTES>>>(
        S.tmp, S.msg, c2c_w1, c2c_b1, c2c_w2, c2c_b2,
        cell_ln_g, cell_ln_b, out_cell, n_cell, 1);
}

// round 7
// speedup vs baseline: 1.6292x; 1.0472x over previous
#include <cuda_runtime.h>

#define D 256
#define MAXN 100000
#define MAXE 301056
#define BM 64
#define KT 16
#define PA 20      // As row stride (floats): banks (20g+t)%32 all distinct
#define PBN 264    // Bs row stride (floats): banks (8*tig+grp)%32 distinct
#define PH 260     // hid row stride (floats): banks (4g+t)%32 distinct

#define ASZ (BM * PA)        // 1280 floats per A buffer
#define BSZ (KT * PBN)       // 4224 floats per B buffer
#define SM_BS (2 * ASZ)                // Bs offset (floats)
#define SM_HID (2 * ASZ + 2 * BSZ)     // hid offset (floats)
#define SMEM_BYTES ((2 * ASZ + 2 * BSZ + BM * PH) * 4)  // 110592 B

// Scratch (allocation-free rule: __device__ globals)
__device__ float g_msg[(size_t)MAXN * D];
__device__ float g_tmp[(size_t)MAXN * D];
__device__ int   g_offs[MAXN + 1];
__device__ int   g_cur[MAXN];
__device__ int   g_eid[MAXE];
__device__ int   g_aux[128];
__device__ int   g_total;

// ---------------------------------------------------------------------------
__global__ void zero_int_kernel(int* __restrict__ p, int n) {
    for (int i = blockIdx.x * blockDim.x + threadIdx.x; i < n;
         i += gridDim.x * blockDim.x)
        p[i] = 0;
}

// count edges per dst
__global__ void count_kernel(const int* __restrict__ dst, int* __restrict__ cnt,
                             int nE) {
    for (int e = blockIdx.x * blockDim.x + threadIdx.x; e < nE;
         e += gridDim.x * blockDim.x)
        atomicAdd(&cnt[dst[e]], 1);
}

// in-place exclusive scan of 1024-elem blocks; aux[b] = block total
__global__ __launch_bounds__(256) void scan_block_kernel(
        int* __restrict__ data, int* __restrict__ aux, int n) {
    __shared__ int wsum[8];
    int t = threadIdx.x;
    int base = blockIdx.x * 1024 + t * 4;
    int v[4];
#pragma unroll
    for (int k = 0; k < 4; k++) v[k] = (base + k < n) ? data[base + k] : 0;
    int tsum = v[0] + v[1] + v[2] + v[3];
    int lane = t & 31, wid = t >> 5;
    int x = tsum;
#pragma unroll
    for (int o = 1; o < 32; o <<= 1) {
        int y = __shfl_up_sync(0xffffffffu, x, o);
        if (lane >= o) x += y;
    }
    int wexc = x - tsum;
    if (lane == 31) wsum[wid] = x;
    __syncthreads();
    if (t == 0) {
        int run = 0;
#pragma unroll
        for (int i = 0; i < 8; i++) { int s = wsum[i]; wsum[i] = run; run += s; }
        aux[blockIdx.x] = run;
    }
    __syncthreads();
    int run = wsum[wid] + wexc;
#pragma unroll
    for (int k = 0; k < 4; k++) {
        if (base + k < n) data[base + k] = run;
        run += v[k];
    }
}

// exclusive scan of aux (nb <= 128), one block of 128 threads
__global__ void scan_aux_kernel(int* __restrict__ aux, int nb,
                                int* __restrict__ total) {
    __shared__ int s[128];
    int t = threadIdx.x;
    int v = (t < nb) ? aux[t] : 0;
    s[t] = v;
    __syncthreads();
    for (int o = 1; o < 128; o <<= 1) {
        int y = (t >= o) ? s[t - o] : 0;
        __syncthreads();
        s[t] += y;
        __syncthreads();
    }
    if (t < nb) aux[t] = s[t] - v;
    if (t == 127) *total = s[127];
}

// offs[i] += aux[i/1024]; cur = offs; offs[n] = total
__global__ void finalize_kernel(int* __restrict__ offs, const int* __restrict__ aux,
                                int* __restrict__ cur, int n,
                                const int* __restrict__ total) {
    int i = blockIdx.x * blockDim.x + threadIdx.x;
    if (i < n) {
        int v = offs[i] + aux[i >> 10];
        offs[i] = v;
        cur[i] = v;
    }
    if (i == 0) offs[n] = *total;
}

// bucket fill: eid[pos within dst bucket] = src
__global__ void fill_kernel(const int* __restrict__ src, const int* __restrict__ dst,
                            int* __restrict__ cur, int* __restrict__ eid, int nE) {
    for (int e = blockIdx.x * blockDim.x + threadIdx.x; e < nE;
         e += gridDim.x * blockDim.x) {
        int p = atomicAdd(&cur[dst[e]], 1);
        eid[p] = src[e];
    }
}

// warp per dst: msg[d] = mean of feat[src] over bucket (0 if empty)
__global__ __launch_bounds__(256) void gather_kernel(
        const float* __restrict__ feat, const int* __restrict__ offs,
        const int* __restrict__ eid, float* __restrict__ msg, int n) {
    int w = (blockIdx.x * blockDim.x + threadIdx.x) >> 5;
    int lane = threadIdx.x & 31;
    if (w >= n) return;
    int s0 = __ldg(offs + w), s1 = __ldg(offs + w + 1);
    float4 a0 = make_float4(0.f, 0.f, 0.f, 0.f);
    float4 a1 = make_float4(0.f, 0.f, 0.f, 0.f);
    int j = s0;
    for (; j + 1 < s1; j += 2) {
        int e0 = __ldg(eid + j), e1 = __ldg(eid + j + 1);
        const float4* r0 = (const float4*)(feat + (size_t)e0 * D);
        const float4* r1 = (const float4*)(feat + (size_t)e1 * D);
        float4 x0 = __ldg(r0 + lane), x1 = __ldg(r0 + lane + 32);
        float4 y0 = __ldg(r1 + lane), y1 = __ldg(r1 + lane + 32);
        a0.x += x0.x + y0.x; a0.y += x0.y + y0.y;
        a0.z += x0.z + y0.z; a0.w += x0.w + y0.w;
        a1.x += x1.x + y1.x; a1.y += x1.y + y1.y;
        a1.z += x1.z + y1.z; a1.w += x1.w + y1.w;
    }
    if (j < s1) {
        int e0 = __ldg(eid + j);
        const float4* r0 = (const float4*)(feat + (size_t)e0 * D);
        float4 x0 = __ldg(r0 + lane), x1 = __ldg(r0 + lane + 32);
        a0.x += x0.x; a0.y += x0.y; a0.z += x0.z; a0.w += x0.w;
        a1.x += x1.x; a1.y += x1.y; a1.z += x1.z; a1.w += x1.w;
    }
    float r = 1.f / (float)max(s1 - s0, 1);
    a0.x *= r; a0.y *= r; a0.z *= r; a0.w *= r;
    a1.x *= r; a1.y *= r; a1.z *= r; a1.w *= r;
    float4* mrow = (float4*)(msg + (size_t)w * D);
    mrow[lane] = a0;
    mrow[lane + 32] = a1;
}

// ---------------------------------------------------------------------------
__device__ __forceinline__ void mma_tf32(float* c, const unsigned* a,
                                         unsigned b0, unsigned b1) {
    asm volatile(
        "mma.sync.aligned.m16n8k8.row.col.f32.tf32.tf32.f32 "
        "{%0,%1,%2,%3}, {%4,%5,%6,%7}, {%8,%9}, {%0,%1,%2,%3};"
        : "+f"(c[0]), "+f"(c[1]), "+f"(c[2]), "+f"(c[3])
        : "r"(a[0]), "r"(a[1]), "r"(a[2]), "r"(a[3]), "r"(b0), "r"(b1));
}

__device__ __forceinline__ void cp16(unsigned dst, const void* src, int nbytes) {
    asm volatile("cp.async.cg.shared.global [%0], [%1], 16, %2;"
                 :: "r"(dst), "l"(src), "r"(nbytes));
}
__device__ __forceinline__ void cp_commit() {
    asm volatile("cp.async.commit_group;");
}
template <int N>
__device__ __forceinline__ void cp_wait() {
    asm volatile("cp.async.wait_group %0;" :: "n"(N));
}

// ---------------------------------------------------------------------------
// Fused MLP: out = [h, msg] @ W1 + b1 -> relu -> @ W2 + b2 -> +h -> (LN).
// 64x256 per block; 8 warps as 2 wm x 4 wn (m=32, n=64 per warp) so each B
// fragment pair feeds two m16 MMAs. Loops ordered so only 2 B regs + 8 A regs
// are live (no spill at the 128-reg cap). tf32 mma, cp.async double-buffered,
// 2 CTAs/SM. msg is pre-normalized.
__global__ __launch_bounds__(256, 2) void mlp_mma_kernel(
    const float* __restrict__ h,
    const float* __restrict__ msg,
    const float* __restrict__ w1, const float* __restrict__ b1,
    const float* __restrict__ w2, const float* __restrict__ b2,
    const float* __restrict__ lng, const float* __restrict__ lnb,
    float* __restrict__ out, int M, int use_ln)
{
    extern __shared__ float smf[];
    float* As  = smf;             // [2][64][PA]
    float* Bs  = smf + SM_BS;     // [2][KT][PBN]
    float* hid = smf + SM_HID;    // [64][PH]
    unsigned sbase = (unsigned)__cvta_generic_to_shared(smf);
    unsigned As_s = sbase;
    unsigned Bs_s = sbase + SM_BS * 4;

    int tid = threadIdx.x;
    int lane = tid & 31, w = tid >> 5;
    int grp = lane >> 2, tig = lane & 3;
    int wm = w & 1, wn = w >> 1;
    int m0 = wm * 32;
    int nbase = wn * 64;
    int row0 = blockIdx.x * BM;

    float acc[2][8][4];
#pragma unroll
    for (int mt = 0; mt < 2; mt++)
#pragma unroll
        for (int i = 0; i < 8; i++)
#pragma unroll
            for (int j = 0; j < 4; j++) acc[mt][i][j] = 0.f;

    // --- cp.async producer indices ---
    int arow = tid >> 2, achunk = tid & 3;            // A: 64 rows x 16 floats
    int aval = (row0 + arow < M) ? 16 : 0;
    int arowc = (row0 + arow < M) ? (row0 + arow) : (M - 1);
    unsigned a_dst0 = As_s + (unsigned)(arow * PA + achunk * 4) * 4;
    int bk = tid >> 4, bseg = tid & 15;               // B: 16 rows x 256 floats
    unsigned b_dst0 = Bs_s + (unsigned)(bk * PBN + bseg * 16) * 4;

    auto issueA = [&](int s, int buf) {
        int k0 = s * KT;
        const float* srcp = (k0 < D)
            ? (h   + (size_t)arowc * D + k0 + achunk * 4)
            : (msg + (size_t)arowc * D + (k0 - D) + achunk * 4);
        cp16(a_dst0 + buf * (ASZ * 4), srcp, aval);
    };
    auto issueB = [&](const float* __restrict__ W, int s, int buf) {
        const float* srcp = W + (size_t)(s * KT + bk) * D + bseg * 16;
        unsigned dst = b_dst0 + buf * (BSZ * 4);
#pragma unroll
        for (int i = 0; i < 4; i++)
            cp16(dst + 16 * i, srcp + 4 * i, 16);
    };

    auto computeStep = [&](const float* __restrict__ Ab, int astride, int kbase,
                           const float* __restrict__ Bb) {
#pragma unroll
        for (int kb = 0; kb < 2; kb++) {
            int lk = kb * 8 + tig;
            int kc = kbase + lk;
            // A fragments for both m16 tiles (8 regs live)
            unsigned a0[4], a1[4];
            a0[0] = __float_as_uint(Ab[(m0 + grp) * astride + kc]);
            a0[1] = __float_as_uint(Ab[(m0 + grp + 8) * astride + kc]);
            a0[2] = __float_as_uint(Ab[(m0 + grp) * astride + kc + 4]);
            a0[3] = __float_as_uint(Ab[(m0 + grp + 8) * astride + kc + 4]);
            a1[0] = __float_as_uint(Ab[(m0 + grp + 16) * astride + kc]);
            a1[1] = __float_as_uint(Ab[(m0 + grp + 24) * astride + kc]);
            a1[2] = __float_as_uint(Ab[(m0 + grp + 16) * astride + kc + 4]);
            a1[3] = __float_as_uint(Ab[(m0 + grp + 24) * astride + kc + 4]);
            const float* Br0 = Bb + lk * PBN;
            const float* Br1 = Bb + (lk + 4) * PBN;
#pragma unroll
            for (int t2 = 0; t2 < 8; t2++) {
                int n = nbase + 8 * t2 + grp;
                unsigned b0 = __float_as_uint(Br0[n]);
                unsigned b1 = __float_as_uint(Br1[n]);
                mma_tf32(acc[0][t2], a0, b0, b1);
                mma_tf32(acc[1][t2], a1, b0, b1);
            }
        }
    };

    // ---- phase 1: hidden = relu(x @ W1 + b1), K = 512, 32 steps ----
    issueA(0, 0); issueB(w1, 0, 0); cp_commit();
#pragma unroll 1
    for (int s = 0; s < 32; s++) {
        if (s < 31) {
            issueA(s + 1, (s + 1) & 1); issueB(w1, s + 1, (s + 1) & 1);
            cp_commit();
            cp_wait<1>();
        } else {
            cp_wait<0>();
        }
        __syncthreads();
        computeStep(As + (s & 1) * ASZ, PA, 0, Bs + (s & 1) * BSZ);
        __syncthreads();
    }

    // prefetch first W2 tile while doing epilogue 1
    issueB(w2, 0, 0); cp_commit();

    // epilogue 1: bias + relu -> hid; reset acc
#pragma unroll
    for (int mt = 0; mt < 2; mt++)
#pragma unroll
    for (int t2 = 0; t2 < 8; t2++) {
        int c = nbase + 8 * t2 + 2 * tig;
        int mr = m0 + 16 * mt + grp;
        float bb0 = __ldg(b1 + c), bb1 = __ldg(b1 + c + 1);
        hid[mr * PH + c]           = fmaxf(acc[mt][t2][0] + bb0, 0.f);
        hid[mr * PH + c + 1]       = fmaxf(acc[mt][t2][1] + bb1, 0.f);
        hid[(mr + 8) * PH + c]     = fmaxf(acc[mt][t2][2] + bb0, 0.f);
        hid[(mr + 8) * PH + c + 1] = fmaxf(acc[mt][t2][3] + bb1, 0.f);
#pragma unroll
        for (int j = 0; j < 4; j++) acc[mt][t2][j] = 0.f;
    }

    // ---- phase 2: acc = hid @ W2, K = 256, 16 steps ----
#pragma unroll 1
    for (int s = 0; s < 16; s++) {
        if (s < 15) {
            issueB(w2, s + 1, (s + 1) & 1);
            cp_commit();
            cp_wait<1>();
        } else {
            cp_wait<0>();
        }
        __syncthreads();   // s==0: also publishes epilogue-1 hid writes
        computeStep(hid, PH, s * KT, Bs + (s & 1) * BSZ);
        __syncthreads();
    }

    // epilogue 2: raw acc -> hid
#pragma unroll
    for (int mt = 0; mt < 2; mt++)
#pragma unroll
    for (int t2 = 0; t2 < 8; t2++) {
        int c = nbase + 8 * t2 + 2 * tig;
        int mr = m0 + 16 * mt + grp;
        hid[mr * PH + c]           = acc[mt][t2][0];
        hid[mr * PH + c + 1]       = acc[mt][t2][1];
        hid[(mr + 8) * PH + c]     = acc[mt][t2][2];
        hid[(mr + 8) * PH + c + 1] = acc[mt][t2][3];
    }
    __syncthreads();

    // output pass: + b2 + residual (+ LN), coalesced; warp w owns rows 8w..8w+7
    for (int q = 0; q < 8; q++) {
        int r = w * 8 + q;
        int row = row0 + r;
        if (row >= M) continue;
        float v[8];
        float sum = 0.f, sq = 0.f;
#pragma unroll
        for (int j = 0; j < 8; j++) {
            int c = lane + 32 * j;
            float x = hid[r * PH + c] + __ldg(b2 + c) + h[(size_t)row * D + c];
            v[j] = x; sum += x; sq += x * x;
        }
        if (use_ln) {
#pragma unroll
            for (int o = 16; o > 0; o >>= 1) {
                sum += __shfl_xor_sync(0xffffffffu, sum, o);
                sq  += __shfl_xor_sync(0xffffffffu, sq, o);
            }
            float mean = sum * (1.f / D);
            float var  = sq * (1.f / D) - mean * mean;
            float rstd = rsqrtf(var + 1e-5f);
#pragma unroll
            for (int j = 0; j < 8; j++) {
                int c = lane + 32 * j;
                v[j] = (v[j] - mean) * rstd * __ldg(lng + c) + __ldg(lnb + c);
            }
        }
#pragma unroll
        for (int j = 0; j < 8; j++)
            out[(size_t)row * D + lane + 32 * j] = v[j];
    }
}

// ---------------------------------------------------------------------------
static inline int cdiv(int a, int b) { return (a + b - 1) / b; }

struct Scratch {
    float *msg, *tmp;
    int *offs, *cur, *eid, *aux, *total;
};

static void aggregate(const float* feat, const int* src, const int* dst,
                      int nE, int n, const Scratch& S) {
    int nb = cdiv(n, 1024);
    zero_int_kernel<<<cdiv(n + 1, 256), 256>>>(S.offs, n + 1);
    count_kernel<<<cdiv(nE, 256), 256>>>(dst, S.offs, nE);
    scan_block_kernel<<<nb, 256>>>(S.offs, S.aux, n);
    scan_aux_kernel<<<1, 128>>>(S.aux, nb, S.total);
    finalize_kernel<<<cdiv(n, 256), 256>>>(S.offs, S.aux, S.cur, n, S.total);
    fill_kernel<<<cdiv(nE, 256), 256>>>(src, dst, S.cur, S.eid, nE);
    gather_kernel<<<cdiv(n * 32, 256), 256>>>(feat, S.offs, S.eid, S.msg, n);
}

extern "C" void kernel_launch(void* const* d_in, const int* in_sizes, int n_in,
                              void* d_out, int out_size) {
    const float* cell_h = (const float*)d_in[0];
    const float* net_h  = (const float*)d_in[1];
    const int* e_c2n = (const int*)d_in[2];
    const int* e_n2c = (const int*)d_in[3];
    const int* e_c2c = (const int*)d_in[4];
    const float* c2n_w1 = (const float*)d_in[5];
    const float* c2n_b1 = (const float*)d_in[6];
    const float* c2n_w2 = (const float*)d_in[7];
    const float* c2n_b2 = (const float*)d_in[8];
    const float* n2c_w1 = (const float*)d_in[9];
    const float* n2c_b1 = (const float*)d_in[10];
    const float* n2c_w2 = (const float*)d_in[11];
    const float* n2c_b2 = (const float*)d_in[12];
    const float* c2c_w1 = (const float*)d_in[13];
    const float* c2c_b1 = (const float*)d_in[14];
    const float* c2c_w2 = (const float*)d_in[15];
    const float* c2c_b2 = (const float*)d_in[16];
    const float* net_ln_g  = (const float*)d_in[17];
    const float* net_ln_b  = (const float*)d_in[18];
    const float* cell_ln_g = (const float*)d_in[19];
    const float* cell_ln_b = (const float*)d_in[20];

    int n_cell = in_sizes[0] / D;
    int n_net  = in_sizes[1] / D;
    int E1 = in_sizes[2] / 2;
    int E2 = in_sizes[3] / 2;
    int E3 = in_sizes[4] / 2;

    float* out = (float*)d_out;
    float* out_cell = out;
    float* out_net  = out + (size_t)n_cell * D;

    static Scratch S = {};
    if (!S.msg) {
        cudaGetSymbolAddress((void**)&S.msg, g_msg);
        cudaGetSymbolAddress((void**)&S.tmp, g_tmp);
        cudaGetSymbolAddress((void**)&S.offs, g_offs);
        cudaGetSymbolAddress((void**)&S.cur, g_cur);
        cudaGetSymbolAddress((void**)&S.eid, g_eid);
        cudaGetSymbolAddress((void**)&S.aux, g_aux);
        cudaGetSymbolAddress((void**)&S.total, g_total);
        cudaFuncSetAttribute(mlp_mma_kernel,
                             cudaFuncAttributeMaxDynamicSharedMemorySize,
                             SMEM_BYTES);
    }

    // Stage 1: cells -> nets, net_h' = LN(net_h + MLP([net_h, mean_msg]))
    aggregate(cell_h, e_c2n, e_c2n + E1, E1, n_net, S);
    mlp_mma_kernel<<<cdiv(n_net, BM), 256, SMEM_BYTES>>>(
        net_h, S.msg, c2n_w1, c2n_b1, c2n_w2, c2n_b2,
        net_ln_g, net_ln_b, out_net, n_net, 1);

    // Stage 2: nets -> cells, cell_tmp = cell_h + MLP([cell_h, mean_msg])
    aggregate(out_net, e_n2c, e_n2c + E2, E2, n_cell, S);
    mlp_mma_kernel<<<cdiv(n_cell, BM), 256, SMEM_BYTES>>>(
        cell_h, S.msg, n2c_w1, n2c_b1, n2c_w2, n2c_b2,
        (const float*)0, (const float*)0, S.tmp, n_cell, 0);

    // Stage 3: cells -> cells, cell_h' = LN(cell_tmp + MLP([cell_tmp, mean_msg]))
    aggregate(S.tmp, e_c2c, e_c2c + E3, E3, n_cell, S);
    mlp_mma_kernel<<<cdiv(n_cell, BM), 256, SMEM_BYTES>>>(
        S.tmp, S.msg, c2c_w1, c2c_b1, c2c_w2, c2c_b2,
        cell_ln_g, cell_ln_b, out_cell, n_cell, 1);
}